// round 10
// baseline (speedup 1.0000x reference)
#include <cuda_runtime.h>
#include <cstdint>

// ---------------------------------------------------------------------------
// MultiHeadedEMA == causal + anti-causal first-order EMA per (head, channel).
//   fwd: u[t] = q*u[t-1] + x[t] ;  rev: u[t] = q*u[t+1] + x[t]
//   out[b,l,d] = sum_h wf[h,d]*uf + wr[h,d]*ur,  w = expansion*reduction*a
// Round-10: full grid barrier replaced with bidirectional decoupled-lookback
// flags (per-chunk publish/wait, geometric window W). Blocks pipeline instead
// of convoying behind the slowest phase1. All 512 blocks co-resident
// (launch_bounds(128,4) -> 592 slots), so waiting on successors is safe.
// Flags are monotonic counters; epoch target = own flag's post-increment
// value -> CUDA-graph replay safe.
// ---------------------------------------------------------------------------

constexpr int kB = 2;
constexpr int kL = 2048;
constexpr int kD = 1024;
constexpr int kH = 8;

constexpr int kChunk   = 32;
constexpr int kNChunk  = kL / kChunk;             // 64
constexpr int kCols    = 256;                     // d-columns per block
constexpr int kThreads = 128;                     // 2 cols/thread -> f32x2
constexpr int kDTiles  = kD / kCols;              // 4
constexpr int kBlocks  = kB * kNChunk * kDTiles;  // 512

// Per-chunk end states (fwd / rev), L2-resident scratch (8 MB).
__device__ __align__(16) float g_sf[kB][kNChunk][kH][kD];
__device__ __align__(16) float g_sr[kB][kNChunk][kH][kD];

// Decoupled-lookback flags: one per (b, dt, c), each +1 per launch.
__device__ unsigned g_ff[kB][kDTiles][kNChunk];
__device__ unsigned g_fr[kB][kDTiles][kNChunk];

using u64 = unsigned long long;

__device__ __forceinline__ u64 pack2(float lo, float hi) {
    u64 r;
    asm("mov.b64 %0, {%1, %2};"
        : "=l"(r) : "r"(__float_as_uint(lo)), "r"(__float_as_uint(hi)));
    return r;
}
__device__ __forceinline__ u64 fma2(u64 a, u64 b, u64 c) {
    u64 r;
    asm("fma.rn.f32x2 %0, %1, %2, %3;" : "=l"(r) : "l"(a), "l"(b), "l"(c));
    return r;
}
__device__ __forceinline__ u64 add2(u64 a, u64 b) {
    u64 r;
    asm("add.rn.f32x2 %0, %1, %2;" : "=l"(r) : "l"(a), "l"(b));
    return r;
}
__device__ __forceinline__ void store_cs(u64* p, u64 v) {
    float2 f;
    f.x = __uint_as_float((unsigned)(v & 0xffffffffull));
    f.y = __uint_as_float((unsigned)(v >> 32));
    __stcs(reinterpret_cast<float2*>(p), f);
}

// fp32 sigmoid; use sigp(-v) for the (1 - sigmoid(v)) term (no cancellation).
__device__ __forceinline__ float sigp(float v) { return 1.0f / (1.0f + expf(-v)); }

// ---------------------------------------------------------------------------
__global__ void __launch_bounds__(kThreads, 4)
ema_fused(const float* __restrict__ x,
          const float* __restrict__ ex,  const float* __restrict__ re,
          const float* __restrict__ al,  const float* __restrict__ da,
          const float* __restrict__ ral, const float* __restrict__ rda,
          float* __restrict__ out)
{
    __shared__ u64 acc[kChunk * kThreads];           // 32 KB fwd partials
    __shared__ float s_q[2][kH], s_a[2][kH], s_qc[2][kH];
    __shared__ int s_W[2];                           // lookback window (chunks)
    __shared__ unsigned s_N;                         // this launch's epoch

    const int tid = threadIdx.x;
    if (tid < 2 * kH) {
        const int dir = tid >= kH;
        const int h   = tid & (kH - 1);
        const float av = dir ? ral[h] : al[h];
        const float dv = dir ? rda[h] : da[h];
        s_a[dir][h] = sigp(av);
        float q = sigp(-av) * sigp(dv);
        s_q[dir][h] = q;
        float qc = q;
#pragma unroll
        for (int k = 0; k < 5; ++k) qc *= qc;        // q^32
        s_qc[dir][h] = qc;
    }

    const int blk = blockIdx.x;
    const int dt = blk & (kDTiles - 1);
    const int c  = (blk >> 2) & (kNChunk - 1);
    const int b  = blk >> 8;

    const u64* xs = reinterpret_cast<const u64*>(
        x + ((size_t)b * kL + (size_t)c * kChunk) * kD + dt * kCols) + tid;
    const int d = dt * kCols + 2 * tid;

    __syncthreads();
    if (tid < 2) {
        float m = 0.0f;
#pragma unroll
        for (int h = 0; h < kH; ++h) m = fmaxf(m, s_qc[tid][h]);
        // W = ceil(ln(1e-8)/ln(qcmax)), clamped to full history.
        int W = kNChunk;
        if (m <= 0.0f) W = 0;
        else {
            float lq = logf(m);
            if (lq < -1e-20f) {
                float w = ceilf(-18.4207f / lq);
                W = (w >= (float)kNChunk) ? kNChunk : (int)w;
            }
        }
        s_W[tid] = W;
    }

    // ================= phase 1a: fwd local scan, publish =====================
    {
        u64 q2[kH], s[kH];
#pragma unroll
        for (int h = 0; h < kH; ++h) {
            float q = s_q[0][h];
            q2[h] = pack2(q, q);
            s[h] = 0ull;
        }
#pragma unroll
        for (int i = 0; i < kChunk; ++i) {
            u64 xv = xs[i * (kD / 2)];               // DRAM/L2, warms L1
#pragma unroll
            for (int h = 0; h < kH; ++h) s[h] = fma2(q2[h], s[h], xv);
        }
#pragma unroll
        for (int h = 0; h < kH; ++h)
            *reinterpret_cast<u64*>(&g_sf[b][c][h][d]) = s[h];
    }
    __threadfence();
    __syncthreads();
    if (tid == 0) s_N = atomicAdd(&g_ff[b][dt][c], 1u) + 1u;   // epoch

    // ================= phase 1b: rev local scan, publish =====================
    {
        u64 q2[kH], s[kH];
#pragma unroll
        for (int h = 0; h < kH; ++h) {
            float q = s_q[1][h];
            q2[h] = pack2(q, q);
            s[h] = 0ull;
        }
#pragma unroll
        for (int i = kChunk - 1; i >= 0; --i) {
            u64 xv = xs[i * (kD / 2)];               // L1 hit
#pragma unroll
            for (int h = 0; h < kH; ++h) s[h] = fma2(q2[h], s[h], xv);
        }
#pragma unroll
        for (int h = 0; h < kH; ++h)
            *reinterpret_cast<u64*>(&g_sr[b][c][h][d]) = s[h];
    }
    __threadfence();
    __syncthreads();                                  // also makes s_N visible
    if (tid == 0) atomicAdd(&g_fr[b][dt][c], 1u);

    const int dh = d >> 1;   // u64 column index
    const u64* bsf = reinterpret_cast<const u64*>(g_sf) +
                     (size_t)b * kNChunk * kH * (kD / 2) + dh;
    const u64* bsr = reinterpret_cast<const u64*>(g_sr) +
                     (size_t)b * kNChunk * kH * (kD / 2) + dh;

    u64* od = reinterpret_cast<u64*>(
        out + ((size_t)b * kL + (size_t)c * kChunk) * kD + dt * kCols) + tid;

    // ================= phase 3a: forward ====================================
    {
        // Load weights first (cold DRAM) so they overlap the flag wait.
        u64 q2[kH], w[kH];
#pragma unroll
        for (int h = 0; h < kH; ++h) {
            float q = s_q[0][h], a = s_a[0][h];
            q2[h] = pack2(q, q);
            float e0 = ex[h * kD + d], e1 = ex[h * kD + d + 1];
            float r0 = re[h * kD + d], r1 = re[h * kD + d + 1];
            w[h] = pack2(e0 * r0 * a, e1 * r1 * a);
        }

        const int Wf = min(s_W[0], c);
        if (tid == 0) {                               // wait on predecessors
            const unsigned N = s_N;
            for (int k = 1; k <= Wf; ++k) {
                volatile unsigned* f = &g_ff[b][dt][c - k];
                while (*f < N) { }
            }
            __threadfence();
        }
        __syncthreads();

        u64 u[kH];
        float wk[kH];
#pragma unroll
        for (int h = 0; h < kH; ++h) { u[h] = 0ull; wk[h] = 1.0f; }
        for (int k = 0; k < Wf; ++k) {                // windowed lookback
            const u64* row = bsf + (size_t)(c - 1 - k) * kH * (kD / 2);
#pragma unroll
            for (int h = 0; h < kH; ++h) {
                u64 sv = row[h * (kD / 2)];
                u[h] = fma2(pack2(wk[h], wk[h]), sv, u[h]);
                wk[h] *= s_qc[0][h];
            }
        }

#pragma unroll
        for (int i = 0; i < kChunk; ++i) {
            u64 xv = xs[i * (kD / 2)];                 // L1 hit
            u64 fs = 0ull;
#pragma unroll
            for (int h = 0; h < kH; ++h) {
                u[h] = fma2(q2[h], u[h], xv);
                fs   = fma2(w[h], u[h], fs);
            }
            acc[i * kThreads + tid] = fs;              // smem partials
        }
    }

    // ================= phase 3b: reverse + final store ======================
    {
        u64 q2[kH], w[kH];
#pragma unroll
        for (int h = 0; h < kH; ++h) {
            float q = s_q[1][h], a = s_a[1][h];
            q2[h] = pack2(q, q);
            float e0 = ex[(kH + h) * kD + d], e1 = ex[(kH + h) * kD + d + 1];
            float r0 = re[(kH + h) * kD + d], r1 = re[(kH + h) * kD + d + 1];
            w[h] = pack2(e0 * r0 * a, e1 * r1 * a);
        }

        const int Wr = min(s_W[1], kNChunk - 1 - c);
        if (tid == 0) {                               // wait on successors
            const unsigned N = s_N;
            for (int k = 1; k <= Wr; ++k) {
                volatile unsigned* f = &g_fr[b][dt][c + k];
                while (*f < N) { }
            }
            __threadfence();
        }
        __syncthreads();

        u64 u[kH];
        float wk[kH];
#pragma unroll
        for (int h = 0; h < kH; ++h) { u[h] = 0ull; wk[h] = 1.0f; }
        for (int k = 0; k < Wr; ++k) {                // windowed lookback
            const u64* row = bsr + (size_t)(c + 1 + k) * kH * (kD / 2);
#pragma unroll
            for (int h = 0; h < kH; ++h) {
                u64 sv = row[h * (kD / 2)];
                u[h] = fma2(pack2(wk[h], wk[h]), sv, u[h]);
                wk[h] *= s_qc[1][h];
            }
        }

#pragma unroll
        for (int i = kChunk - 1; i >= 0; --i) {
            u64 xv = xs[i * (kD / 2)];                 // L1 hit
            u64 rs = 0ull;
#pragma unroll
            for (int h = 0; h < kH; ++h) {
                u[h] = fma2(q2[h], u[h], xv);
                rs   = fma2(w[h], u[h], rs);
            }
            store_cs(od + i * (kD / 2),
                     add2(acc[i * kThreads + tid], rs));  // out written once
        }
    }
}

// ---------------------------------------------------------------------------
extern "C" void kernel_launch(void* const* d_in, const int* in_sizes, int n_in,
                              void* d_out, int out_size)
{
    const float* x   = (const float*)d_in[0];
    const float* ex  = (const float*)d_in[1];
    const float* re  = (const float*)d_in[2];
    const float* al  = (const float*)d_in[3];
    const float* da  = (const float*)d_in[4];
    const float* ral = (const float*)d_in[5];
    const float* rda = (const float*)d_in[6];
    float* out = (float*)d_out;

    ema_fused<<<kBlocks, kThreads>>>(x, ex, re, al, da, ral, rda, out);
}

// round 11
// speedup vs baseline: 1.0234x; 1.0234x over previous
#include <cuda_runtime.h>
#include <cstdint>

// ---------------------------------------------------------------------------
// MultiHeadedEMA == causal + anti-causal first-order EMA per (head, channel).
//   fwd: u[t] = q*u[t-1] + x[t] ;  rev: u[t] = q*u[t+1] + x[t]
//   out[b,l,d] = sum_h wf[h,d]*uf + wr[h,d]*ur,  w = expansion*reduction*a
// Round-11: TWO lean kernels (boundary = free barrier), each with a small
// register footprint for high occupancy. kChunk=16 -> 1024 blocks.
//   A: per-chunk fwd/rev aggregates (DRAM-latency phase, ~70 regs, 28 w/SM)
//   B: windowed geometric lookback (qc = q^16) + seeded rescan + fused output
// Fused-kernel variants were pinned at 16 warps/SM by 128-reg state; this
// split removes that cap.
// ---------------------------------------------------------------------------

constexpr int kB = 2;
constexpr int kL = 2048;
constexpr int kD = 1024;
constexpr int kH = 8;

constexpr int kChunk   = 16;
constexpr int kNChunk  = kL / kChunk;             // 128
constexpr int kCols    = 256;                     // d-columns per block
constexpr int kThreads = 128;                     // 2 cols/thread -> f32x2
constexpr int kDTiles  = kD / kCols;              // 4
constexpr int kBlocks  = kB * kNChunk * kDTiles;  // 1024

// Per-chunk end states (fwd / rev), L2-resident scratch (16 MB).
__device__ __align__(16) float g_sf[kB][kNChunk][kH][kD];
__device__ __align__(16) float g_sr[kB][kNChunk][kH][kD];

using u64 = unsigned long long;

__device__ __forceinline__ u64 pack2(float lo, float hi) {
    u64 r;
    asm("mov.b64 %0, {%1, %2};"
        : "=l"(r) : "r"(__float_as_uint(lo)), "r"(__float_as_uint(hi)));
    return r;
}
__device__ __forceinline__ u64 fma2(u64 a, u64 b, u64 c) {
    u64 r;
    asm("fma.rn.f32x2 %0, %1, %2, %3;" : "=l"(r) : "l"(a), "l"(b), "l"(c));
    return r;
}
__device__ __forceinline__ u64 add2(u64 a, u64 b) {
    u64 r;
    asm("add.rn.f32x2 %0, %1, %2;" : "=l"(r) : "l"(a), "l"(b));
    return r;
}
__device__ __forceinline__ void store_cs(u64* p, u64 v) {
    float2 f;
    f.x = __uint_as_float((unsigned)(v & 0xffffffffull));
    f.y = __uint_as_float((unsigned)(v >> 32));
    __stcs(reinterpret_cast<float2*>(p), f);
}

// fp32 sigmoid; use sigp(-v) for the (1 - sigmoid(v)) term (no cancellation).
__device__ __forceinline__ float sigp(float v) { return 1.0f / (1.0f + expf(-v)); }

// ---------------------------------------------------------------------------
// Kernel A: per-chunk local scans (zero-init), publish fwd/rev end states.
// x chunk cached in registers; x read from DRAM exactly once.
// ---------------------------------------------------------------------------
__global__ void __launch_bounds__(kThreads)
ema_agg(const float* __restrict__ x,
        const float* __restrict__ al,  const float* __restrict__ da,
        const float* __restrict__ ral, const float* __restrict__ rda)
{
    __shared__ float s_q[2][kH];

    const int tid = threadIdx.x;
    if (tid < 2 * kH) {
        const int dir = tid >= kH;
        const int h   = tid & (kH - 1);
        const float av = dir ? ral[h] : al[h];
        const float dv = dir ? rda[h] : da[h];
        s_q[dir][h] = sigp(-av) * sigp(dv);
    }

    const int blk = blockIdx.x;
    const int dt = blk & (kDTiles - 1);
    const int c  = (blk >> 2) & (kNChunk - 1);
    const int b  = blk >> 9;

    const u64* xs = reinterpret_cast<const u64*>(
        x + ((size_t)b * kL + (size_t)c * kChunk) * kD + dt * kCols) + tid;
    const int d = dt * kCols + 2 * tid;

    // Batch all 16 x loads (max MLP, hides DRAM latency).
    u64 xv[kChunk];
#pragma unroll
    for (int i = 0; i < kChunk; ++i) xv[i] = xs[i * (kD / 2)];

    __syncthreads();

    u64 q2[kH], s[kH];
#pragma unroll
    for (int h = 0; h < kH; ++h) {
        float q = s_q[0][h];
        q2[h] = pack2(q, q);
        s[h] = 0ull;
    }
#pragma unroll
    for (int i = 0; i < kChunk; ++i)
#pragma unroll
        for (int h = 0; h < kH; ++h) s[h] = fma2(q2[h], s[h], xv[i]);
#pragma unroll
    for (int h = 0; h < kH; ++h)
        *reinterpret_cast<u64*>(&g_sf[b][c][h][d]) = s[h];

#pragma unroll
    for (int h = 0; h < kH; ++h) {
        float q = s_q[1][h];
        q2[h] = pack2(q, q);
        s[h] = 0ull;
    }
#pragma unroll
    for (int i = kChunk - 1; i >= 0; --i)
#pragma unroll
        for (int h = 0; h < kH; ++h) s[h] = fma2(q2[h], s[h], xv[i]);
#pragma unroll
    for (int h = 0; h < kH; ++h)
        *reinterpret_cast<u64*>(&g_sr[b][c][h][d]) = s[h];
}

// ---------------------------------------------------------------------------
// Kernel B: windowed lookback over aggregates (geometric truncation at 1e-8,
// falls back to full history if q ~ 1) + seeded rescan + fused output.
// ---------------------------------------------------------------------------
__global__ void __launch_bounds__(kThreads)
ema_out(const float* __restrict__ x,
        const float* __restrict__ ex,  const float* __restrict__ re,
        const float* __restrict__ al,  const float* __restrict__ da,
        const float* __restrict__ ral, const float* __restrict__ rda,
        float* __restrict__ out)
{
    __shared__ u64 acc[kChunk * kThreads];           // 16 KB fwd partials
    __shared__ float s_q[2][kH], s_a[2][kH], s_qc[2][kH];
    __shared__ int s_W[2];

    const int tid = threadIdx.x;
    if (tid < 2 * kH) {
        const int dir = tid >= kH;
        const int h   = tid & (kH - 1);
        const float av = dir ? ral[h] : al[h];
        const float dv = dir ? rda[h] : da[h];
        s_a[dir][h] = sigp(av);
        float q = sigp(-av) * sigp(dv);
        s_q[dir][h] = q;
        float qc = q;
#pragma unroll
        for (int k = 0; k < 4; ++k) qc *= qc;        // q^16
        s_qc[dir][h] = qc;
    }
    __syncthreads();
    if (tid < 2) {
        float m = 0.0f;
#pragma unroll
        for (int h = 0; h < kH; ++h) m = fmaxf(m, s_qc[tid][h]);
        // W = ceil(ln(1e-8)/ln(qcmax)), clamped to full history.
        int W = kNChunk;
        if (m <= 0.0f) W = 0;
        else {
            float lq = logf(m);
            if (lq < -1e-20f) {
                float w = ceilf(-18.4207f / lq);
                W = (w >= (float)kNChunk) ? kNChunk : (int)w;
            }
        }
        s_W[tid] = W;
    }

    const int blk = blockIdx.x;
    const int dt = blk & (kDTiles - 1);
    const int c  = (blk >> 2) & (kNChunk - 1);
    const int b  = blk >> 9;

    const u64* xs = reinterpret_cast<const u64*>(
        x + ((size_t)b * kL + (size_t)c * kChunk) * kD + dt * kCols) + tid;
    const int d = dt * kCols + 2 * tid;
    const int dh = d >> 1;

    const u64* bsf = reinterpret_cast<const u64*>(g_sf) +
                     (size_t)b * kNChunk * kH * (kD / 2) + dh;
    const u64* bsr = reinterpret_cast<const u64*>(g_sr) +
                     (size_t)b * kNChunk * kH * (kD / 2) + dh;

    u64* od = reinterpret_cast<u64*>(
        out + ((size_t)b * kL + (size_t)c * kChunk) * kD + dt * kCols) + tid;

    __syncthreads();

    // ================= forward: lookback prefix + rescan ====================
    {
        const int Wf = min(s_W[0], c);
        u64 u[kH];
        float wk[kH];
#pragma unroll
        for (int h = 0; h < kH; ++h) { u[h] = 0ull; wk[h] = 1.0f; }
        for (int k = 0; k < Wf; ++k) {
            const u64* row = bsf + (size_t)(c - 1 - k) * kH * (kD / 2);
#pragma unroll
            for (int h = 0; h < kH; ++h) {
                u64 sv = row[h * (kD / 2)];
                u[h] = fma2(pack2(wk[h], wk[h]), sv, u[h]);
                wk[h] *= s_qc[0][h];
            }
        }

        u64 q2[kH], w[kH];
#pragma unroll
        for (int h = 0; h < kH; ++h) {
            float q = s_q[0][h], a = s_a[0][h];
            q2[h] = pack2(q, q);
            float e0 = ex[h * kD + d], e1 = ex[h * kD + d + 1];
            float r0 = re[h * kD + d], r1 = re[h * kD + d + 1];
            w[h] = pack2(e0 * r0 * a, e1 * r1 * a);
        }
#pragma unroll
        for (int i = 0; i < kChunk; ++i) {
            u64 xv = xs[i * (kD / 2)];               // L2-hot from kernel A
            u64 fs = 0ull;
#pragma unroll
            for (int h = 0; h < kH; ++h) {
                u[h] = fma2(q2[h], u[h], xv);
                fs   = fma2(w[h], u[h], fs);
            }
            acc[i * kThreads + tid] = fs;
        }
    }

    // ================= reverse: lookback prefix + rescan + store ============
    {
        const int Wr = min(s_W[1], kNChunk - 1 - c);
        u64 u[kH];
        float wk[kH];
#pragma unroll
        for (int h = 0; h < kH; ++h) { u[h] = 0ull; wk[h] = 1.0f; }
        for (int k = 0; k < Wr; ++k) {
            const u64* row = bsr + (size_t)(c + 1 + k) * kH * (kD / 2);
#pragma unroll
            for (int h = 0; h < kH; ++h) {
                u64 sv = row[h * (kD / 2)];
                u[h] = fma2(pack2(wk[h], wk[h]), sv, u[h]);
                wk[h] *= s_qc[1][h];
            }
        }

        u64 q2[kH], w[kH];
#pragma unroll
        for (int h = 0; h < kH; ++h) {
            float q = s_q[1][h], a = s_a[1][h];
            q2[h] = pack2(q, q);
            float e0 = ex[(kH + h) * kD + d], e1 = ex[(kH + h) * kD + d + 1];
            float r0 = re[(kH + h) * kD + d], r1 = re[(kH + h) * kD + d + 1];
            w[h] = pack2(e0 * r0 * a, e1 * r1 * a);
        }
#pragma unroll
        for (int i = kChunk - 1; i >= 0; --i) {
            u64 xv = xs[i * (kD / 2)];               // L1 hit (fwd pass warmed)
            u64 rs = 0ull;
#pragma unroll
            for (int h = 0; h < kH; ++h) {
                u[h] = fma2(q2[h], u[h], xv);
                rs   = fma2(w[h], u[h], rs);
            }
            store_cs(od + i * (kD / 2),
                     add2(acc[i * kThreads + tid], rs));  // out written once
        }
    }
}

// ---------------------------------------------------------------------------
extern "C" void kernel_launch(void* const* d_in, const int* in_sizes, int n_in,
                              void* d_out, int out_size)
{
    const float* x   = (const float*)d_in[0];
    const float* ex  = (const float*)d_in[1];
    const float* re  = (const float*)d_in[2];
    const float* al  = (const float*)d_in[3];
    const float* da  = (const float*)d_in[4];
    const float* ral = (const float*)d_in[5];
    const float* rda = (const float*)d_in[6];
    float* out = (float*)d_out;

    ema_agg<<<kBlocks, kThreads>>>(x, al, da, ral, rda);
    ema_out<<<kBlocks, kThreads>>>(x, ex, re, al, da, ral, rda, out);
}